// round 15
// baseline (speedup 1.0000x reference)
#include <cuda_runtime.h>
#include <cuda_bf16.h>

#define N_GENE 4762
#define N_CELL 847
#define NROW (N_CELL + N_GENE)
#define D 256
#define E_MAX 200064
#define NSUB 8
#define TM 64
#define NBLK 148
#define NT1 1024
#define KC 16

// ---------------- device scratch (zero-init at load; k_post cleanup restores) --
__device__ float g_norm_gsrc[N_GENE];
__device__ float g_norm_cdst[N_CELL];
__device__ float g_norm_csrc[N_CELL];
__device__ float g_norm_gdst[N_GENE];
__device__ int   g_subdeg_c[N_CELL * NSUB];
__device__ int   g_subdeg_g[N_GENE * NSUB];
__device__ int   g_subdeg_gsrc[N_GENE * NSUB];
__device__ int   g_subdeg_csrc[N_CELL * NSUB];
__device__ int   g_offs_c[N_CELL * NSUB + 1];
__device__ int   g_offs_g[N_GENE * NSUB + 1];
__device__ int   g_cursor_c[N_CELL * NSUB];
__device__ int   g_cursor_g[N_GENE * NSUB];
__device__ int   g_csr_g2c[E_MAX];
__device__ int   g_csr_c2g[E_MAX];
__device__ float g_agg_c[N_CELL * D];
__device__ float g_agg_g[N_GENE * D];
__device__ float g_part0[NROW * D];
__device__ float g_part1[NROW * D];
__device__ float g_sg[N_GENE];
__device__ float g_sc[N_CELL];
__device__ int   g_bsum[2 * NBLK];

// grid barrier (monotonic generation; valid across graph replays)
__device__ unsigned g_cnt = 0;
__device__ volatile unsigned g_gen = 0;

#define GSYNC() do {                                                          \
    ++ep;                                                                     \
    __syncthreads();                                                          \
    if (threadIdx.x == 0) {                                                   \
        __threadfence();                                                      \
        unsigned t = atomicAdd(&g_cnt, 1u);                                   \
        if ((t % NBLK) == NBLK - 1) { __threadfence(); g_gen = ep; }          \
        else { while ((int)(g_gen - ep) < 0) __nanosleep(64); }               \
        __threadfence();                                                      \
    }                                                                         \
    __syncthreads();                                                          \
} while (0)

// ---------------- helpers ----------------
__device__ __forceinline__ void ffma2(unsigned long long& d, unsigned long long a,
                                      unsigned long long b) {
    asm("fma.rn.f32x2 %0, %1, %2, %3;" : "=l"(d) : "l"(a), "l"(b), "l"(d));
}
__device__ __forceinline__ unsigned smem_u32(const void* p) {
    return (unsigned)__cvta_generic_to_shared(p);
}
__device__ __forceinline__ void cp_async16(unsigned dst, const void* src) {
    asm volatile("cp.async.ca.shared.global [%0], [%1], 16;" :: "r"(dst), "l"(src));
}
__device__ __forceinline__ void cp_commit() {
    asm volatile("cp.async.commit_group;");
}
__device__ __forceinline__ void cp_wait0() {
    asm volatile("cp.async.wait_group 0;");
}

// ---------------- launch 1: cooperative deg + scan + norms ----------------
__device__ __forceinline__ int coop_scan_chunk(const int* __restrict__ deg,
                                               int* __restrict__ offs,
                                               int L, int bid, int tid, int* ws) {
    int chunk = (L + NBLK - 1) / NBLK;
    int start = bid * chunk;
    int i = start + tid;
    int v = (tid < chunk && i < L) ? deg[i] : 0;

    int lane = tid & 31, w = tid >> 5;
    int incl = v;
#pragma unroll
    for (int o = 1; o < 32; o <<= 1) {
        int t = __shfl_up_sync(0xffffffffu, incl, o);
        if (lane >= o) incl += t;
    }
    if (lane == 31) ws[w] = incl;
    __syncthreads();
    if (w == 0) {
        int t0 = ws[lane];
        int inc2 = t0;
#pragma unroll
        for (int o = 1; o < 32; o <<= 1) {
            int t = __shfl_up_sync(0xffffffffu, inc2, o);
            if (lane >= o) inc2 += t;
        }
        ws[lane] = inc2 - t0;
        if (lane == 31) ws[32] = inc2;
    }
    __syncthreads();
    int tot = ws[32];
    if (tid < chunk && i < L) offs[i] = ws[w] + (incl - v);
    __syncthreads();
    return tot;
}

__device__ __forceinline__ void coop_add_base(int* __restrict__ offs, int L,
                                              int slot, int bid, int tid,
                                              int mytot, int* sred) {
    int chunk = (L + NBLK - 1) / NBLK;
    int start = bid * chunk;
    int end = min(L, start + chunk);
    if (tid < 32) {
        int s = 0;
        for (int k = tid; k < bid; k += 32) s += g_bsum[slot * NBLK + k];
#pragma unroll
        for (int o = 16; o; o >>= 1) s += __shfl_xor_sync(0xffffffffu, s, o);
        if (tid == 0) sred[0] = s;
    }
    __syncthreads();
    int base = sred[0];
    int i = start + tid;
    if (tid < chunk && i < end) offs[i] += base;
    if (tid == 0 && end == L && start < L) offs[L] = base + mytot;
    __syncthreads();
}

__global__ void __launch_bounds__(NT1, 1)
k_pre(const int* __restrict__ s1, const int* __restrict__ d1, int E1,
      const int* __restrict__ s2, const int* __restrict__ d2, int E2) {
    __shared__ int ws[40];
    int bid = blockIdx.x, tid = threadIdx.x;
    unsigned ep = g_gen;

    for (int i = bid * NT1 + tid; i < E1 + E2; i += NBLK * NT1) {
        if (i < E1) {
            int sub = i & (NSUB - 1);
            atomicAdd(&g_subdeg_gsrc[s1[i] * NSUB + sub], 1);
            atomicAdd(&g_subdeg_c[d1[i] * NSUB + sub], 1);
        } else {
            int j = i - E1;
            int sub = j & (NSUB - 1);
            atomicAdd(&g_subdeg_csrc[s2[j] * NSUB + sub], 1);
            atomicAdd(&g_subdeg_g[d2[j] * NSUB + sub], 1);
        }
    }
    GSYNC();

    int tot_c = coop_scan_chunk(g_subdeg_c, g_offs_c, N_CELL * NSUB, bid, tid, ws);
    int tot_g = coop_scan_chunk(g_subdeg_g, g_offs_g, N_GENE * NSUB, bid, tid, ws);
    if (tid == 0) { g_bsum[bid] = tot_c; g_bsum[NBLK + bid] = tot_g; }

    for (int i = bid * NT1 + tid; i < N_CELL; i += NBLK * NT1) {
        int a0 = 0, a1 = 0;
#pragma unroll
        for (int k = 0; k < NSUB; k++) {
            a0 += g_subdeg_c[i * NSUB + k];
            a1 += g_subdeg_csrc[i * NSUB + k];
        }
        g_norm_cdst[i] = rsqrtf(fmaxf((float)a0, 1.0f));
        g_norm_csrc[i] = rsqrtf(fmaxf((float)a1, 1.0f));
    }
    for (int i = bid * NT1 + tid; i < N_GENE; i += NBLK * NT1) {
        int a0 = 0, a1 = 0;
#pragma unroll
        for (int k = 0; k < NSUB; k++) {
            a0 += g_subdeg_g[i * NSUB + k];
            a1 += g_subdeg_gsrc[i * NSUB + k];
        }
        g_norm_gdst[i] = rsqrtf(fmaxf((float)a0, 1.0f));
        g_norm_gsrc[i] = rsqrtf(fmaxf((float)a1, 1.0f));
    }
    GSYNC();

    coop_add_base(g_offs_c, N_CELL * NSUB, 0, bid, tid, tot_c, ws);
    coop_add_base(g_offs_g, N_GENE * NSUB, 1, bid, tid, tot_g, ws);
}

// ---------------- launch 2: CSR fill ----------------
__global__ void k_fill(const int* __restrict__ s1, const int* __restrict__ d1, int E1,
                       const int* __restrict__ s2, const int* __restrict__ d2, int E2) {
    int i = blockIdx.x * blockDim.x + threadIdx.x;
    if (i < E1) {
        int s = s1[i], d = d1[i];
        int bkt = d * NSUB + (i & (NSUB - 1));
        int p = atomicAdd(&g_cursor_c[bkt], 1);
        g_csr_g2c[g_offs_c[bkt] + p] = s;
    } else if (i < E1 + E2) {
        int j = i - E1;
        int s = s2[j], d = d2[j];
        int bkt = d * NSUB + (j & (NSUB - 1));
        int p = atomicAdd(&g_cursor_g[bkt], 1);
        g_csr_c2g[g_offs_g[bkt] + p] = s;
    }
}

// ---------------- launch 3: aggregation (at LTS roofline) ----------
__global__ void k_agg(const float* __restrict__ gene_emb,
                      const float* __restrict__ cell_emb) {
    int b = blockIdx.x, tid = threadIdx.x;
    const float* emb; const int* csr; const float* nsrc;
    float* outp; float nd; int beg, end;
    if (b < N_CELL) {
        emb = gene_emb; csr = g_csr_g2c; nsrc = g_norm_gsrc;
        beg = g_offs_c[b * NSUB]; end = g_offs_c[b * NSUB + NSUB];
        nd = g_norm_cdst[b]; outp = g_agg_c + b * D;
    } else {
        int r = b - N_CELL;
        emb = cell_emb; csr = g_csr_c2g; nsrc = g_norm_csrc;
        beg = g_offs_g[r * NSUB]; end = g_offs_g[r * NSUB + NSUB];
        nd = g_norm_gdst[r]; outp = g_agg_g + r * D;
    }

    __shared__ int   sidx[256];
    __shared__ float snrm[256];
    float acc = 0.0f;

    for (int base = beg; base < end; base += 256) {
        int m = end - base; if (m > 256) m = 256;
        __syncthreads();
        if (tid < m) {
            int idx = csr[base + tid];
            sidx[tid] = idx;
            snrm[tid] = nsrc[idx];
        }
        __syncthreads();
        int j = 0;
        for (; j + 16 <= m; j += 16) {
            float f[16];
#pragma unroll
            for (int u = 0; u < 16; u++) f[u] = emb[sidx[j + u] * D + tid];
#pragma unroll
            for (int u = 0; u < 16; u++) acc = fmaf(f[u], snrm[j + u], acc);
        }
        for (; j + 4 <= m; j += 4) {
            float f0 = emb[sidx[j + 0] * D + tid];
            float f1 = emb[sidx[j + 1] * D + tid];
            float f2 = emb[sidx[j + 2] * D + tid];
            float f3 = emb[sidx[j + 3] * D + tid];
            acc = fmaf(f0, snrm[j + 0], acc);
            acc = fmaf(f1, snrm[j + 1], acc);
            acc = fmaf(f2, snrm[j + 2], acc);
            acc = fmaf(f3, snrm[j + 3], acc);
        }
        for (; j < m; j++) acc = fmaf(emb[sidx[j] * D + tid], snrm[j], acc);
    }

    outp[tid] = acc * nd;
}

// ---------------- launch 4 (PROFILED SLOT): GEMM, TM=64 split-K ------------
// 178 blocks: tile t = blk>>1 over 89 row tiles, half h = blk&1 over K halves.
// Lane-pair rows fully used (no padding). Writes raw f32x2 partials.
#define NTILE ((N_CELL + TM - 1) / TM + (N_GENE + TM - 1) / TM)   // 14+75=89
__global__ void __launch_bounds__(256, 1)
k_gemm(const float* __restrict__ W_g2c, const float* __restrict__ W_c2g) {
    const int CB = (N_CELL + TM - 1) / TM;   // 14
    int blk = blockIdx.x, tid = threadIdx.x;
    int h = blk & 1;
    int t = blk >> 1;

    const float* A; const float* W;
    int n, row0, rbase;
    if (t < CB) {
        A = g_agg_c; W = W_g2c; n = N_CELL; row0 = t * TM; rbase = 0;
    } else {
        A = g_agg_g; W = W_c2g; n = N_GENE; row0 = (t - CB) * TM; rbase = N_CELL;
    }
    float* part = h ? g_part1 : g_part0;
    int kh0 = h * 128;          // this block's K window: [kh0, kh0+128)

    __shared__ float sAd[2][KC][128];   // dup pairs, 2x8KB
    __shared__ float sW[2][KC][256];    // 2x16KB

    int lane = tid & 31;
    int w = tid >> 5;
    int wc = w * 32;

    unsigned long long acc0[16], acc1[16];
#pragma unroll
    for (int i = 0; i < 16; i++) { acc0[i] = 0ull; acc1[i] = 0ull; }

    int a_row  = tid >> 2;           // 0..63
    int a_kseg = (tid & 3) * 4;      // 0,4,8,12
    const float4* Wv4 = (const float4*)W;

    // ---- prologue: stage chunk 0 ----
    {
        int gr = row0 + a_row;
        float4 v = (gr < n) ? *(const float4*)&A[gr * D + kh0 + a_kseg]
                            : make_float4(0.f, 0.f, 0.f, 0.f);
        *(float2*)&sAd[0][a_kseg + 0][2 * a_row] = make_float2(v.x, v.x);
        *(float2*)&sAd[0][a_kseg + 1][2 * a_row] = make_float2(v.y, v.y);
        *(float2*)&sAd[0][a_kseg + 2][2 * a_row] = make_float2(v.z, v.z);
        *(float2*)&sAd[0][a_kseg + 3][2 * a_row] = make_float2(v.w, v.w);
        unsigned wbase = smem_u32(&sW[0][0][0]);
        const float4* src = Wv4 + kh0 * 64;
#pragma unroll
        for (int i = 0; i < 4; i++) {
            int idx = tid + i * 256;
            cp_async16(wbase + idx * 16, src + idx);
        }
        cp_commit();
        cp_wait0();
    }
    __syncthreads();

    for (int c = 0; c < 8; c++) {
        int cur = c & 1, nxt = cur ^ 1;
        int kc_next = kh0 + (c + 1) * KC;
        float4 vA;
        if (c < 7) {
            int gr = row0 + a_row;
            vA = (gr < n) ? *(const float4*)&A[gr * D + kc_next + a_kseg]
                          : make_float4(0.f, 0.f, 0.f, 0.f);
            unsigned wbase = smem_u32(&sW[nxt][0][0]);
            const float4* src = Wv4 + kc_next * 64;
#pragma unroll
            for (int i = 0; i < 4; i++) {
                int idx = tid + i * 256;
                cp_async16(wbase + idx * 16, src + idx);
            }
            cp_commit();
        }

        {
            const float (*cA)[128] = sAd[cur];
            const float (*cW)[256] = sW[cur];
            unsigned long long a0 = *(const unsigned long long*)&cA[0][2 * lane];
            unsigned long long a1 = *(const unsigned long long*)&cA[0][64 + 2 * lane];
            ulonglong2 q0 = ((const ulonglong2*)&cW[0][wc])[0];
            ulonglong2 q1 = ((const ulonglong2*)&cW[0][wc])[1];
            ulonglong2 q2 = ((const ulonglong2*)&cW[0][wc])[2];
            ulonglong2 q3 = ((const ulonglong2*)&cW[0][wc])[3];
            ulonglong2 q4 = ((const ulonglong2*)&cW[0][wc])[4];
            ulonglong2 q5 = ((const ulonglong2*)&cW[0][wc])[5];
            ulonglong2 q6 = ((const ulonglong2*)&cW[0][wc])[6];
            ulonglong2 q7 = ((const ulonglong2*)&cW[0][wc])[7];
#pragma unroll
            for (int k = 0; k < KC; k++) {
                unsigned long long na0 = 0, na1 = 0;
                ulonglong2 n0 = {0,0}, n1 = {0,0}, n2 = {0,0}, n3 = {0,0};
                ulonglong2 n4 = {0,0}, n5 = {0,0}, n6 = {0,0}, n7 = {0,0};
                if (k < KC - 1) {
                    na0 = *(const unsigned long long*)&cA[k + 1][2 * lane];
                    na1 = *(const unsigned long long*)&cA[k + 1][64 + 2 * lane];
                    const ulonglong2* wr = (const ulonglong2*)&cW[k + 1][wc];
                    n0 = wr[0]; n1 = wr[1]; n2 = wr[2]; n3 = wr[3];
                    n4 = wr[4]; n5 = wr[5]; n6 = wr[6]; n7 = wr[7];
                }
                ffma2(acc0[0], a0, q0.x);  ffma2(acc0[1], a0, q0.y);
                ffma2(acc0[2], a0, q1.x);  ffma2(acc0[3], a0, q1.y);
                ffma2(acc0[4], a0, q2.x);  ffma2(acc0[5], a0, q2.y);
                ffma2(acc0[6], a0, q3.x);  ffma2(acc0[7], a0, q3.y);
                ffma2(acc0[8], a0, q4.x);  ffma2(acc0[9], a0, q4.y);
                ffma2(acc0[10], a0, q5.x); ffma2(acc0[11], a0, q5.y);
                ffma2(acc0[12], a0, q6.x); ffma2(acc0[13], a0, q6.y);
                ffma2(acc0[14], a0, q7.x); ffma2(acc0[15], a0, q7.y);
                ffma2(acc1[0], a1, q0.x);  ffma2(acc1[1], a1, q0.y);
                ffma2(acc1[2], a1, q1.x);  ffma2(acc1[3], a1, q1.y);
                ffma2(acc1[4], a1, q2.x);  ffma2(acc1[5], a1, q2.y);
                ffma2(acc1[6], a1, q3.x);  ffma2(acc1[7], a1, q3.y);
                ffma2(acc1[8], a1, q4.x);  ffma2(acc1[9], a1, q4.y);
                ffma2(acc1[10], a1, q5.x); ffma2(acc1[11], a1, q5.y);
                ffma2(acc1[12], a1, q6.x); ffma2(acc1[13], a1, q6.y);
                ffma2(acc1[14], a1, q7.x); ffma2(acc1[15], a1, q7.y);
                a0 = na0; a1 = na1;
                q0 = n0; q1 = n1; q2 = n2; q3 = n3;
                q4 = n4; q5 = n5; q6 = n6; q7 = n7;
            }
        }

        if (c < 7) {
            *(float2*)&sAd[nxt][a_kseg + 0][2 * a_row] = make_float2(vA.x, vA.x);
            *(float2*)&sAd[nxt][a_kseg + 1][2 * a_row] = make_float2(vA.y, vA.y);
            *(float2*)&sAd[nxt][a_kseg + 2][2 * a_row] = make_float2(vA.z, vA.z);
            *(float2*)&sAd[nxt][a_kseg + 3][2 * a_row] = make_float2(vA.w, vA.w);
            cp_wait0();
            __syncthreads();
        }
    }

    // ---- write raw partials (STG.64 per f32x2 pair) ----
    int gr0 = row0 + lane;
    int gr1 = row0 + 32 + lane;
    if (gr0 < n) {
        unsigned long long* pp = (unsigned long long*)&part[(rbase + gr0) * D + wc];
#pragma unroll
        for (int i = 0; i < 16; i++) pp[i] = acc0[i];
    }
    if (gr1 < n) {
        unsigned long long* pp = (unsigned long long*)&part[(rbase + gr1) * D + wc];
#pragma unroll
        for (int i = 0; i < 16; i++) pp[i] = acc1[i];
    }
}

// ---------------- launch 5: combine + bias/relu/rowdot, GSYNC, scores ------
__global__ void __launch_bounds__(256, 1)
k_post(const float* __restrict__ b_g2c, const float* __restrict__ b_c2g,
       const float* __restrict__ Wp, const float* __restrict__ bp,
       const int* __restrict__ dsrc, const int* __restrict__ ddst,
       float* __restrict__ score, float* __restrict__ h_gene,
       float* __restrict__ h_cell, int E3) {
    __shared__ float sred[8];
    int bid = blockIdx.x, tid = threadIdx.x;
    int lane = tid & 31, w = tid >> 5;
    unsigned ep = g_gen;

    // Phase A: per-row combine (block = one row per iter)
    for (int r = bid; r < NROW; r += NBLK) {
        const float* bias; float* O; float* sv; int lr, wpoff;
        if (r < N_CELL) { bias = b_g2c; O = h_cell; sv = g_sc; lr = r; wpoff = 256; }
        else            { bias = b_c2g; O = h_gene; sv = g_sg; lr = r - N_CELL; wpoff = 0; }

        float v = g_part0[r * D + tid] + g_part1[r * D + tid] + bias[tid];
        float hv = fmaxf(v, 0.0f);
        O[lr * D + tid] = hv;
        float p = hv * Wp[wpoff + tid];
#pragma unroll
        for (int o = 16; o; o >>= 1) p += __shfl_xor_sync(0xffffffffu, p, o);
        if (lane == 0) sred[w] = p;
        __syncthreads();
        if (tid == 0) {
            float s = 0.0f;
#pragma unroll
            for (int k = 0; k < 8; k++) s += sred[k];
            sv[lr] = s;
        }
        __syncthreads();
    }
    GSYNC();

    // Phase B: edge scores + scratch cleanup
    float b = bp[0];
    for (int i = bid * 256 + tid; i < E3; i += NBLK * 256)
        score[i] = g_sg[dsrc[i]] + g_sc[ddst[i]] + b;
    for (int i = bid * 256 + tid; i < N_CELL * NSUB; i += NBLK * 256) {
        g_subdeg_c[i] = 0; g_subdeg_csrc[i] = 0; g_cursor_c[i] = 0;
    }
    for (int i = bid * 256 + tid; i < N_GENE * NSUB; i += NBLK * 256) {
        g_subdeg_g[i] = 0; g_subdeg_gsrc[i] = 0; g_cursor_g[i] = 0;
    }
}

// ---------------- launch ----------------
extern "C" void kernel_launch(void* const* d_in, const int* in_sizes, int n_in,
                              void* d_out, int out_size) {
    const float* gene_emb = (const float*)d_in[0];
    const float* cell_emb = (const float*)d_in[1];
    const float* W_g2c    = (const float*)d_in[2];
    const float* b_g2c    = (const float*)d_in[3];
    const float* W_c2g    = (const float*)d_in[4];
    const float* b_c2g    = (const float*)d_in[5];
    const float* Wp       = (const float*)d_in[6];
    const float* bp       = (const float*)d_in[7];
    const int* g2c_src    = (const int*)d_in[8];
    const int* g2c_dst    = (const int*)d_in[9];
    const int* c2g_src    = (const int*)d_in[10];
    const int* c2g_dst    = (const int*)d_in[11];
    const int* dec_src    = (const int*)d_in[12];
    const int* dec_dst    = (const int*)d_in[13];

    int E1 = in_sizes[8];
    int E2 = in_sizes[10];
    int E3 = in_sizes[12];

    float* out    = (float*)d_out;
    float* score  = out;
    float* h_gene = out + E3;
    float* h_cell = out + E3 + (long)N_GENE * D;

    k_pre<<<NBLK, NT1>>>(g2c_src, g2c_dst, E1, c2g_src, c2g_dst, E2);
    k_fill<<<(E1 + E2 + 255) / 256, 256>>>(g2c_src, g2c_dst, E1, c2g_src, c2g_dst, E2);
    k_agg<<<N_CELL + N_GENE, 256>>>(gene_emb, cell_emb);
    k_gemm<<<2 * NTILE, 256>>>(W_g2c, W_c2g);
    k_post<<<NBLK, 256>>>(b_g2c, b_c2g, Wp, bp, dec_src, dec_dst,
                          score, h_gene, h_cell, E3);
}

// round 16
// speedup vs baseline: 1.2786x; 1.2786x over previous
#include <cuda_runtime.h>
#include <cuda_bf16.h>

#define N_GENE 4762
#define N_CELL 847
#define D 256
#define E_MAX 200064
#define NSUB 8
#define TM 40
#define NBLK 148
#define NT1 1024
#define KC 16

// ---------------- device scratch (zero-init at load; k_score cleanup restores) --
__device__ float g_norm_gsrc[N_GENE];
__device__ float g_norm_cdst[N_CELL];
__device__ float g_norm_csrc[N_CELL];
__device__ float g_norm_gdst[N_GENE];
__device__ int   g_subdeg_c[N_CELL * NSUB];
__device__ int   g_subdeg_g[N_GENE * NSUB];
__device__ int   g_subdeg_gsrc[N_GENE * NSUB];
__device__ int   g_subdeg_csrc[N_CELL * NSUB];
__device__ int   g_offs_c[N_CELL * NSUB + 1];
__device__ int   g_offs_g[N_GENE * NSUB + 1];
__device__ int   g_cursor_c[N_CELL * NSUB];
__device__ int   g_cursor_g[N_GENE * NSUB];
__device__ int   g_csr_g2c[E_MAX];
__device__ int   g_csr_c2g[E_MAX];
__device__ float g_agg_c[N_CELL * D];
__device__ float g_agg_g[N_GENE * D];
__device__ float g_sg[N_GENE];
__device__ float g_sc[N_CELL];
__device__ int   g_bsum[2 * NBLK];

// grid barrier (monotonic generation; valid across graph replays)
__device__ unsigned g_cnt = 0;
__device__ volatile unsigned g_gen = 0;

#define GSYNC() do {                                                          \
    ++ep;                                                                     \
    __syncthreads();                                                          \
    if (threadIdx.x == 0) {                                                   \
        __threadfence();                                                      \
        unsigned t = atomicAdd(&g_cnt, 1u);                                   \
        if ((t % NBLK) == NBLK - 1) { __threadfence(); g_gen = ep; }          \
        else { while ((int)(g_gen - ep) < 0) __nanosleep(64); }               \
        __threadfence();                                                      \
    }                                                                         \
    __syncthreads();                                                          \
} while (0)

// ---------------- helpers ----------------
__device__ __forceinline__ void ffma2(unsigned long long& d, unsigned long long a,
                                      unsigned long long b) {
    asm("fma.rn.f32x2 %0, %1, %2, %3;" : "=l"(d) : "l"(a), "l"(b), "l"(d));
}
__device__ __forceinline__ void unpack2(unsigned long long v, float& lo, float& hi) {
    asm("mov.b64 {%0, %1}, %2;" : "=f"(lo), "=f"(hi) : "l"(v));
}
__device__ __forceinline__ unsigned smem_u32(const void* p) {
    return (unsigned)__cvta_generic_to_shared(p);
}
__device__ __forceinline__ void cp_async16(unsigned dst, const void* src) {
    asm volatile("cp.async.ca.shared.global [%0], [%1], 16;" :: "r"(dst), "l"(src));
}
__device__ __forceinline__ void cp_commit() {
    asm volatile("cp.async.commit_group;");
}
__device__ __forceinline__ void cp_wait0() {
    asm volatile("cp.async.wait_group 0;");
}

// ---------------- launch 1: cooperative deg + scan + norms + FILL ----------
__device__ __forceinline__ int coop_scan_chunk(const int* __restrict__ deg,
                                               int* __restrict__ offs,
                                               int L, int bid, int tid, int* ws) {
    int chunk = (L + NBLK - 1) / NBLK;
    int start = bid * chunk;
    int i = start + tid;
    int v = (tid < chunk && i < L) ? deg[i] : 0;

    int lane = tid & 31, w = tid >> 5;
    int incl = v;
#pragma unroll
    for (int o = 1; o < 32; o <<= 1) {
        int t = __shfl_up_sync(0xffffffffu, incl, o);
        if (lane >= o) incl += t;
    }
    if (lane == 31) ws[w] = incl;
    __syncthreads();
    if (w == 0) {
        int t0 = ws[lane];
        int inc2 = t0;
#pragma unroll
        for (int o = 1; o < 32; o <<= 1) {
            int t = __shfl_up_sync(0xffffffffu, inc2, o);
            if (lane >= o) inc2 += t;
        }
        ws[lane] = inc2 - t0;
        if (lane == 31) ws[32] = inc2;
    }
    __syncthreads();
    int tot = ws[32];
    if (tid < chunk && i < L) offs[i] = ws[w] + (incl - v);
    __syncthreads();
    return tot;
}

__device__ __forceinline__ void coop_add_base(int* __restrict__ offs, int L,
                                              int slot, int bid, int tid,
                                              int mytot, int* sred) {
    int chunk = (L + NBLK - 1) / NBLK;
    int start = bid * chunk;
    int end = min(L, start + chunk);
    if (tid < 32) {
        int s = 0;
        for (int k = tid; k < bid; k += 32) s += g_bsum[slot * NBLK + k];
#pragma unroll
        for (int o = 16; o; o >>= 1) s += __shfl_xor_sync(0xffffffffu, s, o);
        if (tid == 0) sred[0] = s;
    }
    __syncthreads();
    int base = sred[0];
    int i = start + tid;
    if (tid < chunk && i < end) offs[i] += base;
    if (tid == 0 && end == L && start < L) offs[L] = base + mytot;
    __syncthreads();
}

__global__ void __launch_bounds__(NT1, 1)
k_pre(const int* __restrict__ s1, const int* __restrict__ d1, int E1,
      const int* __restrict__ s2, const int* __restrict__ d2, int E2) {
    __shared__ int ws[40];
    int bid = blockIdx.x, tid = threadIdx.x;
    unsigned ep = g_gen;

    // P0: degrees (spread sub-bucket atomics)
    for (int i = bid * NT1 + tid; i < E1 + E2; i += NBLK * NT1) {
        if (i < E1) {
            int sub = i & (NSUB - 1);
            atomicAdd(&g_subdeg_gsrc[s1[i] * NSUB + sub], 1);
            atomicAdd(&g_subdeg_c[d1[i] * NSUB + sub], 1);
        } else {
            int j = i - E1;
            int sub = j & (NSUB - 1);
            atomicAdd(&g_subdeg_csrc[s2[j] * NSUB + sub], 1);
            atomicAdd(&g_subdeg_g[d2[j] * NSUB + sub], 1);
        }
    }
    GSYNC();

    // P1a: chunk scans + norms
    int tot_c = coop_scan_chunk(g_subdeg_c, g_offs_c, N_CELL * NSUB, bid, tid, ws);
    int tot_g = coop_scan_chunk(g_subdeg_g, g_offs_g, N_GENE * NSUB, bid, tid, ws);
    if (tid == 0) { g_bsum[bid] = tot_c; g_bsum[NBLK + bid] = tot_g; }

    for (int i = bid * NT1 + tid; i < N_CELL; i += NBLK * NT1) {
        int a0 = 0, a1 = 0;
#pragma unroll
        for (int k = 0; k < NSUB; k++) {
            a0 += g_subdeg_c[i * NSUB + k];
            a1 += g_subdeg_csrc[i * NSUB + k];
        }
        g_norm_cdst[i] = rsqrtf(fmaxf((float)a0, 1.0f));
        g_norm_csrc[i] = rsqrtf(fmaxf((float)a1, 1.0f));
    }
    for (int i = bid * NT1 + tid; i < N_GENE; i += NBLK * NT1) {
        int a0 = 0, a1 = 0;
#pragma unroll
        for (int k = 0; k < NSUB; k++) {
            a0 += g_subdeg_g[i * NSUB + k];
            a1 += g_subdeg_gsrc[i * NSUB + k];
        }
        g_norm_gdst[i] = rsqrtf(fmaxf((float)a0, 1.0f));
        g_norm_gsrc[i] = rsqrtf(fmaxf((float)a1, 1.0f));
    }
    GSYNC();

    // P1b: add global bases
    coop_add_base(g_offs_c, N_CELL * NSUB, 0, bid, tid, tot_c, ws);
    coop_add_base(g_offs_g, N_GENE * NSUB, 1, bid, tid, tot_g, ws);
    GSYNC();

    // P2: CSR fill (counting sort by dst sub-bucket)
    for (int i = bid * NT1 + tid; i < E1 + E2; i += NBLK * NT1) {
        if (i < E1) {
            int s = s1[i], d = d1[i];
            int bkt = d * NSUB + (i & (NSUB - 1));
            int p = atomicAdd(&g_cursor_c[bkt], 1);
            g_csr_g2c[g_offs_c[bkt] + p] = s;
        } else {
            int j = i - E1;
            int s = s2[j], d = d2[j];
            int bkt = d * NSUB + (j & (NSUB - 1));
            int p = atomicAdd(&g_cursor_g[bkt], 1);
            g_csr_c2g[g_offs_g[bkt] + p] = s;
        }
    }
}

// ---------------- launch 2: aggregation (at LTS roofline) ----------
__global__ void k_agg(const float* __restrict__ gene_emb,
                      const float* __restrict__ cell_emb) {
    int b = blockIdx.x, tid = threadIdx.x;
    const float* emb; const int* csr; const float* nsrc;
    float* outp; float nd; int beg, end;
    if (b < N_CELL) {
        emb = gene_emb; csr = g_csr_g2c; nsrc = g_norm_gsrc;
        beg = g_offs_c[b * NSUB]; end = g_offs_c[b * NSUB + NSUB];
        nd = g_norm_cdst[b]; outp = g_agg_c + b * D;
    } else {
        int r = b - N_CELL;
        emb = cell_emb; csr = g_csr_c2g; nsrc = g_norm_csrc;
        beg = g_offs_g[r * NSUB]; end = g_offs_g[r * NSUB + NSUB];
        nd = g_norm_gdst[r]; outp = g_agg_g + r * D;
    }

    __shared__ int   sidx[256];
    __shared__ float snrm[256];
    float acc = 0.0f;

    for (int base = beg; base < end; base += 256) {
        int m = end - base; if (m > 256) m = 256;
        __syncthreads();
        if (tid < m) {
            int idx = csr[base + tid];
            sidx[tid] = idx;
            snrm[tid] = nsrc[idx];
        }
        __syncthreads();
        int j = 0;
        for (; j + 16 <= m; j += 16) {
            float f[16];
#pragma unroll
            for (int u = 0; u < 16; u++) f[u] = emb[sidx[j + u] * D + tid];
#pragma unroll
            for (int u = 0; u < 16; u++) acc = fmaf(f[u], snrm[j + u], acc);
        }
        for (; j + 4 <= m; j += 4) {
            float f0 = emb[sidx[j + 0] * D + tid];
            float f1 = emb[sidx[j + 1] * D + tid];
            float f2 = emb[sidx[j + 2] * D + tid];
            float f3 = emb[sidx[j + 3] * D + tid];
            acc = fmaf(f0, snrm[j + 0], acc);
            acc = fmaf(f1, snrm[j + 1], acc);
            acc = fmaf(f2, snrm[j + 2], acc);
            acc = fmaf(f3, snrm[j + 3], acc);
        }
        for (; j < m; j++) acc = fmaf(emb[sidx[j] * D + tid], snrm[j], acc);
    }

    outp[tid] = acc * nd;
}

// ---------------- launch 3: GEMM (R14 best: TM=40, pipelined, dup-A) -------
__global__ void __launch_bounds__(256, 1)
k_gemm(const float* __restrict__ W_g2c, const float* __restrict__ b_g2c,
       const float* __restrict__ W_c2g, const float* __restrict__ b_c2g,
       const float* __restrict__ Wp,
       float* __restrict__ h_cell, float* __restrict__ h_gene) {
    const int CB = (N_CELL + TM - 1) / TM;   // 22
    int blk = blockIdx.x, tid = threadIdx.x;

    const float* A; const float* W; const float* bias; float* O; float* sv;
    int n, row0, wpoff;
    if (blk < CB) {
        A = g_agg_c; W = W_g2c; bias = b_g2c; O = h_cell; sv = g_sc;
        n = N_CELL; row0 = blk * TM; wpoff = 256;
    } else {
        A = g_agg_g; W = W_c2g; bias = b_c2g; O = h_gene; sv = g_sg;
        n = N_GENE; row0 = (blk - CB) * TM; wpoff = 0;
    }

    __shared__ float sAd[2][KC][128];   // dup pairs, 2x8KB
    __shared__ float sW[2][KC][256];    // 2x16KB

    int lane = tid & 31;
    int w = tid >> 5;
    int wc = w * 32;

    unsigned long long acc0[16], acc1[16];
#pragma unroll
    for (int i = 0; i < 16; i++) { acc0[i] = 0ull; acc1[i] = 0ull; }

    int a_row  = tid >> 2;           // 0..63
    int a_kseg = (tid & 3) * 4;      // 0,4,8,12
    const float4* Wv4 = (const float4*)W;

    // prologue: stage chunk 0
    {
        int gr = row0 + a_row;
        float4 v = (a_row < TM && gr < n)
                       ? *(const float4*)&A[gr * D + a_kseg]
                       : make_float4(0.f, 0.f, 0.f, 0.f);
        *(float2*)&sAd[0][a_kseg + 0][2 * a_row] = make_float2(v.x, v.x);
        *(float2*)&sAd[0][a_kseg + 1][2 * a_row] = make_float2(v.y, v.y);
        *(float2*)&sAd[0][a_kseg + 2][2 * a_row] = make_float2(v.z, v.z);
        *(float2*)&sAd[0][a_kseg + 3][2 * a_row] = make_float2(v.w, v.w);
        unsigned wbase = smem_u32(&sW[0][0][0]);
#pragma unroll
        for (int i = 0; i < 4; i++) {
            int idx = tid + i * 256;
            cp_async16(wbase + idx * 16, Wv4 + idx);
        }
        cp_commit();
        cp_wait0();
    }
    __syncthreads();

    for (int c = 0; c < 16; c++) {
        int cur = c & 1, nxt = cur ^ 1;
        int kc_next = (c + 1) * KC;
        float4 vA;
        if (c < 15) {
            int gr = row0 + a_row;
            vA = (a_row < TM && gr < n)
                     ? *(const float4*)&A[gr * D + kc_next + a_kseg]
                     : make_float4(0.f, 0.f, 0.f, 0.f);
            unsigned wbase = smem_u32(&sW[nxt][0][0]);
            const float4* src = Wv4 + kc_next * 64;
#pragma unroll
            for (int i = 0; i < 4; i++) {
                int idx = tid + i * 256;
                cp_async16(wbase + idx * 16, src + idx);
            }
            cp_commit();
        }

        {
            const float (*cA)[128] = sAd[cur];
            const float (*cW)[256] = sW[cur];
            unsigned long long a0 = *(const unsigned long long*)&cA[0][2 * lane];
            unsigned long long a1 = *(const unsigned long long*)&cA[0][64 + 2 * lane];
            ulonglong2 q0 = ((const ulonglong2*)&cW[0][wc])[0];
            ulonglong2 q1 = ((const ulonglong2*)&cW[0][wc])[1];
            ulonglong2 q2 = ((const ulonglong2*)&cW[0][wc])[2];
            ulonglong2 q3 = ((const ulonglong2*)&cW[0][wc])[3];
            ulonglong2 q4 = ((const ulonglong2*)&cW[0][wc])[4];
            ulonglong2 q5 = ((const ulonglong2*)&cW[0][wc])[5];
            ulonglong2 q6 = ((const ulonglong2*)&cW[0][wc])[6];
            ulonglong2 q7 = ((const ulonglong2*)&cW[0][wc])[7];
#pragma unroll
            for (int k = 0; k < KC; k++) {
                unsigned long long na0 = 0, na1 = 0;
                ulonglong2 n0 = {0,0}, n1 = {0,0}, n2 = {0,0}, n3 = {0,0};
                ulonglong2 n4 = {0,0}, n5 = {0,0}, n6 = {0,0}, n7 = {0,0};
                if (k < KC - 1) {
                    na0 = *(const unsigned long long*)&cA[k + 1][2 * lane];
                    na1 = *(const unsigned long long*)&cA[k + 1][64 + 2 * lane];
                    const ulonglong2* wr = (const ulonglong2*)&cW[k + 1][wc];
                    n0 = wr[0]; n1 = wr[1]; n2 = wr[2]; n3 = wr[3];
                    n4 = wr[4]; n5 = wr[5]; n6 = wr[6]; n7 = wr[7];
                }
                ffma2(acc0[0], a0, q0.x);  ffma2(acc0[1], a0, q0.y);
                ffma2(acc0[2], a0, q1.x);  ffma2(acc0[3], a0, q1.y);
                ffma2(acc0[4], a0, q2.x);  ffma2(acc0[5], a0, q2.y);
                ffma2(acc0[6], a0, q3.x);  ffma2(acc0[7], a0, q3.y);
                ffma2(acc0[8], a0, q4.x);  ffma2(acc0[9], a0, q4.y);
                ffma2(acc0[10], a0, q5.x); ffma2(acc0[11], a0, q5.y);
                ffma2(acc0[12], a0, q6.x); ffma2(acc0[13], a0, q6.y);
                ffma2(acc0[14], a0, q7.x); ffma2(acc0[15], a0, q7.y);
                ffma2(acc1[0], a1, q0.x);  ffma2(acc1[1], a1, q0.y);
                ffma2(acc1[2], a1, q1.x);  ffma2(acc1[3], a1, q1.y);
                ffma2(acc1[4], a1, q2.x);  ffma2(acc1[5], a1, q2.y);
                ffma2(acc1[6], a1, q3.x);  ffma2(acc1[7], a1, q3.y);
                ffma2(acc1[8], a1, q4.x);  ffma2(acc1[9], a1, q4.y);
                ffma2(acc1[10], a1, q5.x); ffma2(acc1[11], a1, q5.y);
                ffma2(acc1[12], a1, q6.x); ffma2(acc1[13], a1, q6.y);
                ffma2(acc1[14], a1, q7.x); ffma2(acc1[15], a1, q7.y);
                a0 = na0; a1 = na1;
                q0 = n0; q1 = n1; q2 = n2; q3 = n3;
                q4 = n4; q5 = n5; q6 = n6; q7 = n7;
            }
        }

        if (c < 15) {
            *(float2*)&sAd[nxt][a_kseg + 0][2 * a_row] = make_float2(vA.x, vA.x);
            *(float2*)&sAd[nxt][a_kseg + 1][2 * a_row] = make_float2(vA.y, vA.y);
            *(float2*)&sAd[nxt][a_kseg + 2][2 * a_row] = make_float2(vA.z, vA.z);
            *(float2*)&sAd[nxt][a_kseg + 3][2 * a_row] = make_float2(vA.w, vA.w);
            cp_wait0();
            __syncthreads();
        }
    }

    // epilogue: bias + relu + store + per-lane rowdot
    __syncthreads();
    float (*sred)[9] = (float(*)[9])&sAd[0][0][0];
    int gr0 = row0 + lane;
    int gr1 = row0 + 32 + lane;
    bool v0 = (gr0 < n);
    bool v1 = (lane < TM - 32) && (gr1 < n);

    float p0 = 0.0f, p1 = 0.0f;
#pragma unroll
    for (int i4 = 0; i4 < 8; i4++) {
        int cc = wc + i4 * 4;
        float4 bv = *(const float4*)&bias[cc];
        float4 wv = *(const float4*)&Wp[wpoff + cc];
        float l0, h0, l1, h1;

        unpack2(acc0[2 * i4], l0, h0);
        unpack2(acc0[2 * i4 + 1], l1, h1);
        float4 r0;
        r0.x = fmaxf(l0 + bv.x, 0.0f);
        r0.y = fmaxf(h0 + bv.y, 0.0f);
        r0.z = fmaxf(l1 + bv.z, 0.0f);
        r0.w = fmaxf(h1 + bv.w, 0.0f);
        if (v0) {
            *(float4*)&O[gr0 * D + cc] = r0;
            p0 = fmaf(r0.x, wv.x, p0); p0 = fmaf(r0.y, wv.y, p0);
            p0 = fmaf(r0.z, wv.z, p0); p0 = fmaf(r0.w, wv.w, p0);
        }

        unpack2(acc1[2 * i4], l0, h0);
        unpack2(acc1[2 * i4 + 1], l1, h1);
        float4 r1;
        r1.x = fmaxf(l0 + bv.x, 0.0f);
        r1.y = fmaxf(h0 + bv.y, 0.0f);
        r1.z = fmaxf(l1 + bv.z, 0.0f);
        r1.w = fmaxf(h1 + bv.w, 0.0f);
        if (v1) {
            *(float4*)&O[gr1 * D + cc] = r1;
            p1 = fmaf(r1.x, wv.x, p1); p1 = fmaf(r1.y, wv.y, p1);
            p1 = fmaf(r1.z, wv.z, p1); p1 = fmaf(r1.w, wv.w, p1);
        }
    }

    sred[lane][w] = p0;
    if (lane < TM - 32) sred[32 + lane][w] = p1;
    __syncthreads();
    if (tid < TM) {
        int gr = row0 + tid;
        if (gr < n) {
            float s = 0.0f;
#pragma unroll
            for (int k = 0; k < 8; k++) s += sred[tid][k];
            sv[gr] = s;
        }
    }
}

// ---------------- launch 4: scores + cleanup ----------------
__global__ void k_score(const int* __restrict__ dsrc, const int* __restrict__ ddst,
                        const float* __restrict__ bp, float* __restrict__ out, int E) {
    int i = blockIdx.x * blockDim.x + threadIdx.x;
    if (i < E) out[i] = g_sg[dsrc[i]] + g_sc[ddst[i]] + bp[0];

    if (i < N_CELL * NSUB) { g_subdeg_c[i] = 0; g_subdeg_csrc[i] = 0; g_cursor_c[i] = 0; }
    if (i < N_GENE * NSUB) { g_subdeg_g[i] = 0; g_subdeg_gsrc[i] = 0; g_cursor_g[i] = 0; }
}

// ---------------- launch ----------------
extern "C" void kernel_launch(void* const* d_in, const int* in_sizes, int n_in,
                              void* d_out, int out_size) {
    const float* gene_emb = (const float*)d_in[0];
    const float* cell_emb = (const float*)d_in[1];
    const float* W_g2c    = (const float*)d_in[2];
    const float* b_g2c    = (const float*)d_in[3];
    const float* W_c2g    = (const float*)d_in[4];
    const float* b_c2g    = (const float*)d_in[5];
    const float* Wp       = (const float*)d_in[6];
    const float* bp       = (const float*)d_in[7];
    const int* g2c_src    = (const int*)d_in[8];
    const int* g2c_dst    = (const int*)d_in[9];
    const int* c2g_src    = (const int*)d_in[10];
    const int* c2g_dst    = (const int*)d_in[11];
    const int* dec_src    = (const int*)d_in[12];
    const int* dec_dst    = (const int*)d_in[13];

    int E1 = in_sizes[8];
    int E2 = in_sizes[10];
    int E3 = in_sizes[12];

    float* out    = (float*)d_out;
    float* score  = out;
    float* h_gene = out + E3;
    float* h_cell = out + E3 + (long)N_GENE * D;

    k_pre<<<NBLK, NT1>>>(g2c_src, g2c_dst, E1, c2g_src, c2g_dst, E2);
    k_agg<<<N_CELL + N_GENE, 256>>>(gene_emb, cell_emb);

    const int CB = (N_CELL + TM - 1) / TM;
    const int GB = (N_GENE + TM - 1) / TM;
    k_gemm<<<CB + GB, 256>>>(W_g2c, b_g2c, W_c2g, b_c2g, Wp, h_cell, h_gene);

    k_score<<<(E3 + 255) / 256, 256>>>(dec_src, dec_dst, bp, score, E3);
}

// round 17
// speedup vs baseline: 1.4121x; 1.1044x over previous
#include <cuda_runtime.h>
#include <cuda_fp16.h>

#define N_GENE 4762
#define N_CELL 847
#define D 256
#define E_MAX 200064
#define NSUB 8
#define TM 40
#define NBLK 148
#define NT1 1024
#define KC 16

// ---------------- device scratch (zero-init at load; k_score cleanup restores) --
__device__ float  g_norm_gsrc[N_GENE];
__device__ float  g_norm_cdst[N_CELL];
__device__ float  g_norm_csrc[N_CELL];
__device__ float  g_norm_gdst[N_GENE];
__device__ int    g_subdeg_c[N_CELL * NSUB];
__device__ int    g_subdeg_g[N_GENE * NSUB];
__device__ int    g_subdeg_gsrc[N_GENE * NSUB];
__device__ int    g_subdeg_csrc[N_CELL * NSUB];
__device__ int    g_offs_c[N_CELL * NSUB + 1];
__device__ int    g_offs_g[N_GENE * NSUB + 1];
__device__ int    g_cursor_c[N_CELL * NSUB];
__device__ int    g_cursor_g[N_GENE * NSUB];
__device__ int    g_csr_g2c[E_MAX];
__device__ int    g_csr_c2g[E_MAX];
__device__ __half g_feat_g[N_GENE * D];   // emb * norm_src, fp16
__device__ __half g_feat_c[N_CELL * D];
__device__ float  g_agg_c[N_CELL * D];
__device__ float  g_agg_g[N_GENE * D];
__device__ float  g_sg[N_GENE];
__device__ float  g_sc[N_CELL];
__device__ int    g_bsum[2 * NBLK];

// grid barrier (monotonic generation; valid across graph replays)
__device__ unsigned g_cnt = 0;
__device__ volatile unsigned g_gen = 0;

#define GSYNC() do {                                                          \
    ++ep;                                                                     \
    __syncthreads();                                                          \
    if (threadIdx.x == 0) {                                                   \
        __threadfence();                                                      \
        unsigned t = atomicAdd(&g_cnt, 1u);                                   \
        if ((t % NBLK) == NBLK - 1) { __threadfence(); g_gen = ep; }          \
        else { while ((int)(g_gen - ep) < 0) __nanosleep(64); }               \
        __threadfence();                                                      \
    }                                                                         \
    __syncthreads();                                                          \
} while (0)

// ---------------- helpers ----------------
__device__ __forceinline__ void ffma2(unsigned long long& d, unsigned long long a,
                                      unsigned long long b) {
    asm("fma.rn.f32x2 %0, %1, %2, %3;" : "=l"(d) : "l"(a), "l"(b), "l"(d));
}
__device__ __forceinline__ void unpack2(unsigned long long v, float& lo, float& hi) {
    asm("mov.b64 {%0, %1}, %2;" : "=f"(lo), "=f"(hi) : "l"(v));
}
__device__ __forceinline__ unsigned smem_u32(const void* p) {
    return (unsigned)__cvta_generic_to_shared(p);
}
__device__ __forceinline__ void cp_async16(unsigned dst, const void* src) {
    asm volatile("cp.async.ca.shared.global [%0], [%1], 16;" :: "r"(dst), "l"(src));
}
__device__ __forceinline__ void cp_commit() {
    asm volatile("cp.async.commit_group;");
}
__device__ __forceinline__ void cp_wait0() {
    asm volatile("cp.async.wait_group 0;");
}

// ---------------- launch 1: coop deg + scan + norms + fill + fp16 convert ---
__device__ __forceinline__ int coop_scan_chunk(const int* __restrict__ deg,
                                               int* __restrict__ offs,
                                               int L, int bid, int tid, int* ws) {
    int chunk = (L + NBLK - 1) / NBLK;
    int start = bid * chunk;
    int i = start + tid;
    int v = (tid < chunk && i < L) ? deg[i] : 0;

    int lane = tid & 31, w = tid >> 5;
    int incl = v;
#pragma unroll
    for (int o = 1; o < 32; o <<= 1) {
        int t = __shfl_up_sync(0xffffffffu, incl, o);
        if (lane >= o) incl += t;
    }
    if (lane == 31) ws[w] = incl;
    __syncthreads();
    if (w == 0) {
        int t0 = ws[lane];
        int inc2 = t0;
#pragma unroll
        for (int o = 1; o < 32; o <<= 1) {
            int t = __shfl_up_sync(0xffffffffu, inc2, o);
            if (lane >= o) inc2 += t;
        }
        ws[lane] = inc2 - t0;
        if (lane == 31) ws[32] = inc2;
    }
    __syncthreads();
    int tot = ws[32];
    if (tid < chunk && i < L) offs[i] = ws[w] + (incl - v);
    __syncthreads();
    return tot;
}

__device__ __forceinline__ void coop_add_base(int* __restrict__ offs, int L,
                                              int slot, int bid, int tid,
                                              int mytot, int* sred) {
    int chunk = (L + NBLK - 1) / NBLK;
    int start = bid * chunk;
    int end = min(L, start + chunk);
    if (tid < 32) {
        int s = 0;
        for (int k = tid; k < bid; k += 32) s += g_bsum[slot * NBLK + k];
#pragma unroll
        for (int o = 16; o; o >>= 1) s += __shfl_xor_sync(0xffffffffu, s, o);
        if (tid == 0) sred[0] = s;
    }
    __syncthreads();
    int base = sred[0];
    int i = start + tid;
    if (tid < chunk && i < end) offs[i] += base;
    if (tid == 0 && end == L && start < L) offs[L] = base + mytot;
    __syncthreads();
}

__global__ void __launch_bounds__(NT1, 1)
k_pre(const int* __restrict__ s1, const int* __restrict__ d1, int E1,
      const int* __restrict__ s2, const int* __restrict__ d2, int E2,
      const float* __restrict__ gene_emb, const float* __restrict__ cell_emb) {
    __shared__ int ws[40];
    int bid = blockIdx.x, tid = threadIdx.x;
    unsigned ep = g_gen;

    // P0: degrees (spread sub-bucket atomics)
    for (int i = bid * NT1 + tid; i < E1 + E2; i += NBLK * NT1) {
        if (i < E1) {
            int sub = i & (NSUB - 1);
            atomicAdd(&g_subdeg_gsrc[s1[i] * NSUB + sub], 1);
            atomicAdd(&g_subdeg_c[d1[i] * NSUB + sub], 1);
        } else {
            int j = i - E1;
            int sub = j & (NSUB - 1);
            atomicAdd(&g_subdeg_csrc[s2[j] * NSUB + sub], 1);
            atomicAdd(&g_subdeg_g[d2[j] * NSUB + sub], 1);
        }
    }
    GSYNC();

    // P1a: chunk scans + norms
    int tot_c = coop_scan_chunk(g_subdeg_c, g_offs_c, N_CELL * NSUB, bid, tid, ws);
    int tot_g = coop_scan_chunk(g_subdeg_g, g_offs_g, N_GENE * NSUB, bid, tid, ws);
    if (tid == 0) { g_bsum[bid] = tot_c; g_bsum[NBLK + bid] = tot_g; }

    for (int i = bid * NT1 + tid; i < N_CELL; i += NBLK * NT1) {
        int a0 = 0, a1 = 0;
#pragma unroll
        for (int k = 0; k < NSUB; k++) {
            a0 += g_subdeg_c[i * NSUB + k];
            a1 += g_subdeg_csrc[i * NSUB + k];
        }
        g_norm_cdst[i] = rsqrtf(fmaxf((float)a0, 1.0f));
        g_norm_csrc[i] = rsqrtf(fmaxf((float)a1, 1.0f));
    }
    for (int i = bid * NT1 + tid; i < N_GENE; i += NBLK * NT1) {
        int a0 = 0, a1 = 0;
#pragma unroll
        for (int k = 0; k < NSUB; k++) {
            a0 += g_subdeg_g[i * NSUB + k];
            a1 += g_subdeg_gsrc[i * NSUB + k];
        }
        g_norm_gdst[i] = rsqrtf(fmaxf((float)a0, 1.0f));
        g_norm_gsrc[i] = rsqrtf(fmaxf((float)a1, 1.0f));
    }
    GSYNC();

    // P1b: add global bases
    coop_add_base(g_offs_c, N_CELL * NSUB, 0, bid, tid, tot_c, ws);
    coop_add_base(g_offs_g, N_GENE * NSUB, 1, bid, tid, tot_g, ws);
    GSYNC();

    // P2: CSR fill + fp16 feature conversion (norm_src folded in)
    for (int i = bid * NT1 + tid; i < E1 + E2; i += NBLK * NT1) {
        if (i < E1) {
            int s = s1[i], d = d1[i];
            int bkt = d * NSUB + (i & (NSUB - 1));
            int p = atomicAdd(&g_cursor_c[bkt], 1);
            g_csr_g2c[g_offs_c[bkt] + p] = s;
        } else {
            int j = i - E1;
            int s = s2[j], d = d2[j];
            int bkt = d * NSUB + (j & (NSUB - 1));
            int p = atomicAdd(&g_cursor_g[bkt], 1);
            g_csr_c2g[g_offs_g[bkt] + p] = s;
        }
    }
    {
        // genes: N_GENE*D/2 half2 elements
        __half2* fg = (__half2*)g_feat_g;
        const float2* eg = (const float2*)gene_emb;
        for (int i = bid * NT1 + tid; i < N_GENE * (D / 2); i += NBLK * NT1) {
            float nm = g_norm_gsrc[i >> 7];
            float2 v = eg[i];
            fg[i] = __floats2half2_rn(v.x * nm, v.y * nm);
        }
        __half2* fc = (__half2*)g_feat_c;
        const float2* ec = (const float2*)cell_emb;
        for (int i = bid * NT1 + tid; i < N_CELL * (D / 2); i += NBLK * NT1) {
            float nm = g_norm_csrc[i >> 7];
            float2 v = ec[i];
            fc[i] = __floats2half2_rn(v.x * nm, v.y * nm);
        }
    }
}

// ---------------- launch 2: aggregation (fp16 gather, half bytes) ----------
__global__ void k_agg() {
    int b = blockIdx.x, tid = threadIdx.x;   // 128 threads: col pair 2*tid
    const __half2* feat2; const int* csr;
    float2* outp; float nd; int beg, end;
    if (b < N_CELL) {
        feat2 = (const __half2*)g_feat_g; csr = g_csr_g2c;
        beg = g_offs_c[b * NSUB]; end = g_offs_c[b * NSUB + NSUB];
        nd = g_norm_cdst[b]; outp = (float2*)(g_agg_c + b * D);
    } else {
        int r = b - N_CELL;
        feat2 = (const __half2*)g_feat_c; csr = g_csr_c2g;
        beg = g_offs_g[r * NSUB]; end = g_offs_g[r * NSUB + NSUB];
        nd = g_norm_gdst[r]; outp = (float2*)(g_agg_g + r * D);
    }

    __shared__ int sidx[128];
    float ax = 0.0f, ay = 0.0f;

    for (int base = beg; base < end; base += 128) {
        int m = end - base; if (m > 128) m = 128;
        __syncthreads();
        if (tid < m) sidx[tid] = csr[base + tid] * (D / 2);
        __syncthreads();
        int j = 0;
        for (; j + 16 <= m; j += 16) {
            __half2 f[16];
#pragma unroll
            for (int u = 0; u < 16; u++) f[u] = feat2[sidx[j + u] + tid];
#pragma unroll
            for (int u = 0; u < 16; u++) {
                float2 v = __half22float2(f[u]);
                ax += v.x; ay += v.y;
            }
        }
        for (; j + 4 <= m; j += 4) {
            __half2 f0 = feat2[sidx[j + 0] + tid];
            __half2 f1 = feat2[sidx[j + 1] + tid];
            __half2 f2 = feat2[sidx[j + 2] + tid];
            __half2 f3 = feat2[sidx[j + 3] + tid];
            float2 v0 = __half22float2(f0), v1 = __half22float2(f1);
            float2 v2 = __half22float2(f2), v3 = __half22float2(f3);
            ax += v0.x; ay += v0.y; ax += v1.x; ay += v1.y;
            ax += v2.x; ay += v2.y; ax += v3.x; ay += v3.y;
        }
        for (; j < m; j++) {
            float2 v = __half22float2(feat2[sidx[j] + tid]);
            ax += v.x; ay += v.y;
        }
    }

    float2 o; o.x = ax * nd; o.y = ay * nd;
    outp[tid] = o;
}

// ---------------- launch 3: GEMM (R14 best: TM=40, pipelined, dup-A) -------
__global__ void __launch_bounds__(256, 1)
k_gemm(const float* __restrict__ W_g2c, const float* __restrict__ b_g2c,
       const float* __restrict__ W_c2g, const float* __restrict__ b_c2g,
       const float* __restrict__ Wp,
       float* __restrict__ h_cell, float* __restrict__ h_gene) {
    const int CB = (N_CELL + TM - 1) / TM;   // 22
    int blk = blockIdx.x, tid = threadIdx.x;

    const float* A; const float* W; const float* bias; float* O; float* sv;
    int n, row0, wpoff;
    if (blk < CB) {
        A = g_agg_c; W = W_g2c; bias = b_g2c; O = h_cell; sv = g_sc;
        n = N_CELL; row0 = blk * TM; wpoff = 256;
    } else {
        A = g_agg_g; W = W_c2g; bias = b_c2g; O = h_gene; sv = g_sg;
        n = N_GENE; row0 = (blk - CB) * TM; wpoff = 0;
    }

    __shared__ float sAd[2][KC][128];
    __shared__ float sW[2][KC][256];

    int lane = tid & 31;
    int w = tid >> 5;
    int wc = w * 32;

    unsigned long long acc0[16], acc1[16];
#pragma unroll
    for (int i = 0; i < 16; i++) { acc0[i] = 0ull; acc1[i] = 0ull; }

    int a_row  = tid >> 2;
    int a_kseg = (tid & 3) * 4;
    const float4* Wv4 = (const float4*)W;

    {
        int gr = row0 + a_row;
        float4 v = (a_row < TM && gr < n)
                       ? *(const float4*)&A[gr * D + a_kseg]
                       : make_float4(0.f, 0.f, 0.f, 0.f);
        *(float2*)&sAd[0][a_kseg + 0][2 * a_row] = make_float2(v.x, v.x);
        *(float2*)&sAd[0][a_kseg + 1][2 * a_row] = make_float2(v.y, v.y);
        *(float2*)&sAd[0][a_kseg + 2][2 * a_row] = make_float2(v.z, v.z);
        *(float2*)&sAd[0][a_kseg + 3][2 * a_row] = make_float2(v.w, v.w);
        unsigned wbase = smem_u32(&sW[0][0][0]);
#pragma unroll
        for (int i = 0; i < 4; i++) {
            int idx = tid + i * 256;
            cp_async16(wbase + idx * 16, Wv4 + idx);
        }
        cp_commit();
        cp_wait0();
    }
    __syncthreads();

    for (int c = 0; c < 16; c++) {
        int cur = c & 1, nxt = cur ^ 1;
        int kc_next = (c + 1) * KC;
        float4 vA;
        if (c < 15) {
            int gr = row0 + a_row;
            vA = (a_row < TM && gr < n)
                     ? *(const float4*)&A[gr * D + kc_next + a_kseg]
                     : make_float4(0.f, 0.f, 0.f, 0.f);
            unsigned wbase = smem_u32(&sW[nxt][0][0]);
            const float4* src = Wv4 + kc_next * 64;
#pragma unroll
            for (int i = 0; i < 4; i++) {
                int idx = tid + i * 256;
                cp_async16(wbase + idx * 16, src + idx);
            }
            cp_commit();
        }

        {
            const float (*cA)[128] = sAd[cur];
            const float (*cW)[256] = sW[cur];
            unsigned long long a0 = *(const unsigned long long*)&cA[0][2 * lane];
            unsigned long long a1 = *(const unsigned long long*)&cA[0][64 + 2 * lane];
            ulonglong2 q0 = ((const ulonglong2*)&cW[0][wc])[0];
            ulonglong2 q1 = ((const ulonglong2*)&cW[0][wc])[1];
            ulonglong2 q2 = ((const ulonglong2*)&cW[0][wc])[2];
            ulonglong2 q3 = ((const ulonglong2*)&cW[0][wc])[3];
            ulonglong2 q4 = ((const ulonglong2*)&cW[0][wc])[4];
            ulonglong2 q5 = ((const ulonglong2*)&cW[0][wc])[5];
            ulonglong2 q6 = ((const ulonglong2*)&cW[0][wc])[6];
            ulonglong2 q7 = ((const ulonglong2*)&cW[0][wc])[7];
#pragma unroll
            for (int k = 0; k < KC; k++) {
                unsigned long long na0 = 0, na1 = 0;
                ulonglong2 n0 = {0,0}, n1 = {0,0}, n2 = {0,0}, n3 = {0,0};
                ulonglong2 n4 = {0,0}, n5 = {0,0}, n6 = {0,0}, n7 = {0,0};
                if (k < KC - 1) {
                    na0 = *(const unsigned long long*)&cA[k + 1][2 * lane];
                    na1 = *(const unsigned long long*)&cA[k + 1][64 + 2 * lane];
                    const ulonglong2* wr = (const ulonglong2*)&cW[k + 1][wc];
                    n0 = wr[0]; n1 = wr[1]; n2 = wr[2]; n3 = wr[3];
                    n4 = wr[4]; n5 = wr[5]; n6 = wr[6]; n7 = wr[7];
                }
                ffma2(acc0[0], a0, q0.x);  ffma2(acc0[1], a0, q0.y);
                ffma2(acc0[2], a0, q1.x);  ffma2(acc0[3], a0, q1.y);
                ffma2(acc0[4], a0, q2.x);  ffma2(acc0[5], a0, q2.y);
                ffma2(acc0[6], a0, q3.x);  ffma2(acc0[7], a0, q3.y);
                ffma2(acc0[8], a0, q4.x);  ffma2(acc0[9], a0, q4.y);
                ffma2(acc0[10], a0, q5.x); ffma2(acc0[11], a0, q5.y);
                ffma2(acc0[12], a0, q6.x); ffma2(acc0[13], a0, q6.y);
                ffma2(acc0[14], a0, q7.x); ffma2(acc0[15], a0, q7.y);
                ffma2(acc1[0], a1, q0.x);  ffma2(acc1[1], a1, q0.y);
                ffma2(acc1[2], a1, q1.x);  ffma2(acc1[3], a1, q1.y);
                ffma2(acc1[4], a1, q2.x);  ffma2(acc1[5], a1, q2.y);
                ffma2(acc1[6], a1, q3.x);  ffma2(acc1[7], a1, q3.y);
                ffma2(acc1[8], a1, q4.x);  ffma2(acc1[9], a1, q4.y);
                ffma2(acc1[10], a1, q5.x); ffma2(acc1[11], a1, q5.y);
                ffma2(acc1[12], a1, q6.x); ffma2(acc1[13], a1, q6.y);
                ffma2(acc1[14], a1, q7.x); ffma2(acc1[15], a1, q7.y);
                a0 = na0; a1 = na1;
                q0 = n0; q1 = n1; q2 = n2; q3 = n3;
                q4 = n4; q5 = n5; q6 = n6; q7 = n7;
            }
        }

        if (c < 15) {
            *(float2*)&sAd[nxt][a_kseg + 0][2 * a_row] = make_float2(vA.x, vA.x);
            *(float2*)&sAd[nxt][a_kseg + 1][2 * a_row] = make_float2(vA.y, vA.y);
            *(float2*)&sAd[nxt][a_kseg + 2][2 * a_row] = make_float2(vA.z, vA.z);
            *(float2*)&sAd[nxt][a_kseg + 3][2 * a_row] = make_float2(vA.w, vA.w);
            cp_wait0();
            __syncthreads();
        }
    }

    __syncthreads();
    float (*sred)[9] = (float(*)[9])&sAd[0][0][0];
    int gr0 = row0 + lane;
    int gr1 = row0 + 32 + lane;
    bool v0 = (gr0 < n);
    bool v1 = (lane < TM - 32) && (gr1 < n);

    float p0 = 0.0f, p1 = 0.0f;
#pragma unroll
    for (int i4 = 0; i4 < 8; i4++) {
        int cc = wc + i4 * 4;
        float4 bv = *(const float4*)&bias[cc];
        float4 wv = *(const float4*)&Wp[wpoff + cc];
        float l0, h0, l1, h1;

        unpack2(acc0[2 * i4], l0, h0);
        unpack2(acc0[2 * i4 + 1], l1, h1);
        float4 r0;
        r0.x = fmaxf(l0 + bv.x, 0.0f);
        r0.y = fmaxf(h0 + bv.y, 0.0f);
        r0.z = fmaxf(l1 + bv.z, 0.0f);
        r0.w = fmaxf(h1 + bv.w, 0.0f);
        if (v0) {
            *(float4*)&O[gr0 * D + cc] = r0;
            p0 = fmaf(r0.x, wv.x, p0); p0 = fmaf(r0.y, wv.y, p0);
            p0 = fmaf(r0.z, wv.z, p0); p0 = fmaf(r0.w, wv.w, p0);
        }

        unpack2(acc1[2 * i4], l0, h0);
        unpack2(acc1[2 * i4 + 1], l1, h1);
        float4 r1;
        r1.x = fmaxf(l0 + bv.x, 0.0f);
        r1.y = fmaxf(h0 + bv.y, 0.0f);
        r1.z = fmaxf(l1 + bv.z, 0.0f);
        r1.w = fmaxf(h1 + bv.w, 0.0f);
        if (v1) {
            *(float4*)&O[gr1 * D + cc] = r1;
            p1 = fmaf(r1.x, wv.x, p1); p1 = fmaf(r1.y, wv.y, p1);
            p1 = fmaf(r1.z, wv.z, p1); p1 = fmaf(r1.w, wv.w, p1);
        }
    }

    sred[lane][w] = p0;
    if (lane < TM - 32) sred[32 + lane][w] = p1;
    __syncthreads();
    if (tid < TM) {
        int gr = row0 + tid;
        if (gr < n) {
            float s = 0.0f;
#pragma unroll
            for (int k = 0; k < 8; k++) s += sred[tid][k];
            sv[gr] = s;
        }
    }
}

// ---------------- launch 4: scores (x4 unrolled) + cleanup ----------------
__global__ void k_score(const int* __restrict__ dsrc, const int* __restrict__ ddst,
                        const float* __restrict__ bp, float* __restrict__ out, int E) {
    int i = blockIdx.x * blockDim.x + threadIdx.x;
    int base = i * 4;
    float b = bp[0];
    if (base + 3 < E) {
        int4 s4 = *(const int4*)&dsrc[base];
        int4 d4 = *(const int4*)&ddst[base];
        float g0 = g_sg[s4.x], g1 = g_sg[s4.y], g2 = g_sg[s4.z], g3 = g_sg[s4.w];
        float c0 = g_sc[d4.x], c1 = g_sc[d4.y], c2 = g_sc[d4.z], c3 = g_sc[d4.w];
        float4 o;
        o.x = g0 + c0 + b; o.y = g1 + c1 + b;
        o.z = g2 + c2 + b; o.w = g3 + c3 + b;
        *(float4*)&out[base] = o;
    } else {
        for (int k = base; k < E && k < base + 4; k++)
            out[k] = g_sg[dsrc[k]] + g_sc[ddst[k]] + b;
    }

    if (i < N_CELL * NSUB) { g_subdeg_c[i] = 0; g_subdeg_csrc[i] = 0; g_cursor_c[i] = 0; }
    if (i < N_GENE * NSUB) { g_subdeg_g[i] = 0; g_subdeg_gsrc[i] = 0; g_cursor_g[i] = 0; }
}

// ---------------- launch ----------------
extern "C" void kernel_launch(void* const* d_in, const int* in_sizes, int n_in,
                              void* d_out, int out_size) {
    const float* gene_emb = (const float*)d_in[0];
    const float* cell_emb = (const float*)d_in[1];
    const float* W_g2c    = (const float*)d_in[2];
    const float* b_g2c    = (const float*)d_in[3];
    const float* W_c2g    = (const float*)d_in[4];
    const float* b_c2g    = (const float*)d_in[5];
    const float* Wp       = (const float*)d_in[6];
    const float* bp       = (const float*)d_in[7];
    const int* g2c_src    = (const int*)d_in[8];
    const int* g2c_dst    = (const int*)d_in[9];
    const int* c2g_src    = (const int*)d_in[10];
    const int* c2g_dst    = (const int*)d_in[11];
    const int* dec_src    = (const int*)d_in[12];
    const int* dec_dst    = (const int*)d_in[13];

    int E1 = in_sizes[8];
    int E2 = in_sizes[10];
    int E3 = in_sizes[12];

    float* out    = (float*)d_out;
    float* score  = out;
    float* h_gene = out + E3;
    float* h_cell = out + E3 + (long)N_GENE * D;

    k_pre<<<NBLK, NT1>>>(g2c_src, g2c_dst, E1, c2g_src, c2g_dst, E2,
                         gene_emb, cell_emb);
    k_agg<<<N_CELL + N_GENE, 128>>>();

    const int CB = (N_CELL + TM - 1) / TM;
    const int GB = (N_GENE + TM - 1) / TM;
    k_gemm<<<CB + GB, 256>>>(W_g2c, b_g2c, W_c2g, b_c2g, Wp, h_cell, h_gene);

    // ensure enough threads to cover cleanup arrays (N_GENE*NSUB = 38096)
    int nthr = (E3 + 3) / 4;
    if (nthr < N_GENE * NSUB) nthr = N_GENE * NSUB;
    k_score<<<(nthr + 255) / 256, 256>>>(dec_src, dec_dst, bp, score, E3);
}